// round 15
// baseline (speedup 1.0000x reference)
#include <cuda_runtime.h>
#include <cuda_bf16.h>
#include <math.h>

#define Nn 64
#define Cc 256
#define Tt 64
#define Vv 25
#define Kk 8
#define VNh 5
#define VT 30
#define CG 32
#define HH 8
#define OO 256
#define OG 32
#define TOPK 9

// ---- k_main (MMA) constants (R12 layout) ----
#define TBm 8
#define XSTR 40
#define B2STR 200
#define SM_B2 0
#define SM_AT 12800
#define SM_WT 15360
#define SM_MISC 17920
#define SM_XS 18432
#define SM_BYTES (18432 + 20480)   // 38912

// ---- k_hN smem float offsets ----
#define HN_A 0         // ps 7680 / nd (stride 31, 7440) / tmp (stride 30, 7200)
#define HN_B 7680      // incid 7200
#define HN_VP 14880    // vproj 1920 [k][v][h]
#define HN_W1 16800    // w1a 1920 [q][v]
#define HN_T2 18720    // t2all 512 [k][q]
#define HN_WT 19232    // wt 240
#define HN_RMX 19472   // 240
#define HN_RSUM 19712  // 240
#define HN_DVV 19952   // 240
#define HN_RSS 20192   // 240
#define HN_FLOATS 20432
#define HN_BYTES (HN_FLOATS * 4)   // 81728

// ---------------- device scratch ----------------
__device__ float g_pooled[Nn * Cc * VT];
__device__ float g_adjn[Kk * VT * VT];
__device__ float g_adj[Nn * Kk * VT * VT];

// ---------------- mma helpers ----------------
__device__ __forceinline__ unsigned smaddr(const void* p) {
    return (unsigned)__cvta_generic_to_shared(p);
}
__device__ __forceinline__ void ldsm4(unsigned* r, unsigned a) {
    asm volatile("ldmatrix.sync.aligned.m8n8.x4.shared.b16 {%0,%1,%2,%3}, [%4];"
                 : "=r"(r[0]), "=r"(r[1]), "=r"(r[2]), "=r"(r[3]) : "r"(a));
}
__device__ __forceinline__ void ldsm4t(unsigned* r, unsigned a) {
    asm volatile("ldmatrix.sync.aligned.m8n8.x4.trans.shared.b16 {%0,%1,%2,%3}, [%4];"
                 : "=r"(r[0]), "=r"(r[1]), "=r"(r[2]), "=r"(r[3]) : "r"(a));
}
__device__ __forceinline__ void ldsm2t(unsigned* r, unsigned a) {
    asm volatile("ldmatrix.sync.aligned.m8n8.x2.trans.shared.b16 {%0,%1}, [%2];"
                 : "=r"(r[0]), "=r"(r[1]) : "r"(a));
}
__device__ __forceinline__ void mma16816(float* d, const unsigned* a, const unsigned* b) {
    asm volatile(
        "mma.sync.aligned.m16n8k16.row.col.f32.bf16.bf16.f32 "
        "{%0,%1,%2,%3}, {%4,%5,%6,%7}, {%8,%9}, {%0,%1,%2,%3};"
        : "+f"(d[0]), "+f"(d[1]), "+f"(d[2]), "+f"(d[3])
        : "r"(a[0]), "r"(a[1]), "r"(a[2]), "r"(a[3]), "r"(b[0]), "r"(b[1]));
}

// ---------------- kernel 1: pooled mean (+ adjn/tail in extra block) ----------------
__global__ __launch_bounds__(256) void k_pool(const float* __restrict__ x,
                                              const float* __restrict__ hj,
                                              const float* __restrict__ adjc,
                                              const float* __restrict__ ei,
                                              float* __restrict__ out, int tail) {
    int tid = threadIdx.x;
    if (blockIdx.x == Nn * Cc / 2) {
        if (tid < Kk * VT) {
            int base = tid * VT;
            float row[VT];
            float s = 0.f;
#pragma unroll
            for (int w = 0; w < VT; w++) {
                float v = ei[base + w] * adjc[base + w];
                row[w] = v;
                s += fabsf(v);
            }
            float inv = 1.f / (s + 1e-8f);
#pragma unroll
            for (int w = 0; w < VT; w++) g_adjn[base + w] = row[w] * inv;
        }
        for (int i = tid; i < tail && i < VNh * Cc; i += 256)
            out[(size_t)Nn * OO * Tt * Vv + i] = hj[i];
        return;
    }
    __shared__ float sred[2][100];
    int half = tid >> 7;
    int j = tid & 127;
    int nc = blockIdx.x * 2 + half;
    const float* base = x + (size_t)nc * (Tt * Vv);
    if (j < 100) {
        float s0 = 0.f, s1 = 0.f, s2 = 0.f, s3 = 0.f;
#pragma unroll
        for (int r = 0; r < 16; r += 4) {
            s0 += base[(r + 0) * 100 + j];
            s1 += base[(r + 1) * 100 + j];
            s2 += base[(r + 2) * 100 + j];
            s3 += base[(r + 3) * 100 + j];
        }
        sred[half][j] = (s0 + s1) + (s2 + s3);
    }
    __syncthreads();
    if (j < Vv) {
        float s = (sred[half][j] + sred[half][j + 25]) +
                  (sred[half][j + 50] + sred[half][j + 75]);
        g_pooled[nc * VT + j] = s * (1.f / (float)Tt);
    } else if (j < VT) {
        g_pooled[nc * VT + j] = hj[(j - Vv) * Cc + (nc & (Cc - 1))];
    }
}

// ---------------- kernel 2: fused hyper, one block per n ----------------
__global__ __launch_bounds__(256) void k_hN(
    const float* __restrict__ tvw, const float* __restrict__ tvb,
    const float* __restrict__ t1w, const float* __restrict__ t1b,
    const float* __restrict__ t2w, const float* __restrict__ t2b,
    const float* __restrict__ alpha) {
    extern __shared__ float sh[];
    float* A = sh + HN_A;        // ps -> nd -> tmp
    float* incid = sh + HN_B;
    float* vp = sh + HN_VP;      // [k*240 + v*8 + h]
    float* w1a = sh + HN_W1;     // [q*30 + v]
    float* t2 = sh + HN_T2;      // [k*64 + q]
    float* wt = sh + HN_WT;      // [k*30 + v]
    float* rmx = sh + HN_RMX;
    float* rsum = sh + HN_RSUM;
    float* dvv = sh + HN_DVV;
    float* rss = sh + HN_RSS;

    int n = blockIdx.x;
    int tid = threadIdx.x;

    // phase 0: load pooled (A = ps) + t2w
    for (int e = tid; e < Cc * VT; e += 256) A[e] = g_pooled[n * (Cc * VT) + e];
    for (int e = tid; e < Kk * Kk * HH; e += 256) t2[e] = t2w[e];
    __syncthreads();

    // phase 1: vproj (all k) + w1 (all q), from ps
    for (int e = tid; e < 2 * 1920; e += 256) {
        if (e < 1920) {
            int k = e / 240;
            int e2 = e - k * 240;
            int v = e2 >> 3, h = e2 & 7;
            float acc = tvb[k * HH + h];
            const float* w = tvw + (k * HH + h) * CG;
            const float* p = A + (k * CG) * VT + v;
#pragma unroll 8
            for (int c = 0; c < CG; c++) acc += p[c * VT] * w[c];
            vp[k * 240 + v * 8 + h] = acc;
        } else {
            int e3 = e - 1920;
            int q = e3 / VT, v = e3 - (e3 / VT) * VT;
            int k2 = q >> 3;
            float acc = t1b[q];
            const float* w = t1w + q * CG;
            const float* p = A + (k2 * CG) * VT + v;
#pragma unroll 8
            for (int c = 0; c < CG; c++) acc += p[c * VT] * w[c];
            w1a[q * VT + v] = (acc >= 0.f) ? acc : 0.01f * acc;
        }
    }
    __syncthreads();   // ps dead -> A reusable as nd

    // phase 2: wt (240 threads) + nd (all threads, A stride 31)
    if (tid < Kk * VT) {
        int k = tid / VT, v = tid - (tid / VT) * VT;
        float acc = t2b[k];
        const float* w = t2 + k * (Kk * HH);
#pragma unroll 8
        for (int q = 0; q < Kk * HH; q++) acc += w1a[q * VT + v] * w[q];
        wt[tid] = tanhf(acc);
    }
    for (int e = tid; e < Kk * VT * VT; e += 256) {
        int k = e / 900;
        int r = e - k * 900;
        int u = r / VT, w = r - u * VT;
        const float* pu = vp + k * 240 + u * 8;
        const float* pw = vp + k * 240 + w * 8;
        float d2 = 0.f;
#pragma unroll
        for (int h = 0; h < HH; h++) {
            float df = pu[h] - pw[h];
            d2 += df * df;
        }
        A[k * 930 + u * 31 + w] = (d2 > 0.f) ? -sqrtf(d2) : 0.f;
    }
    __syncthreads();

    // phase 3: row max
    if (tid < Kk * VT) {
        int k = tid / VT, u = tid - (tid / VT) * VT;
        const float* row = A + k * 930 + u * 31;
        float m = -INFINITY;
#pragma unroll 6
        for (int w = 0; w < VT; w++) m = fmaxf(m, row[w]);
        rmx[tid] = m;
    }
    __syncthreads();

    // phase 4: rank selection + exp -> incid
    for (int e = tid; e < Kk * VT * VT; e += 256) {
        int k = e / 900;
        int r = e - k * 900;
        int u = r / VT, w = r - u * VT;
        const float* row = A + k * 930 + u * 31;
        float v = row[w];
        int rank = 0;
#pragma unroll 6
        for (int w2 = 0; w2 < VT; w2++) {
            float v2 = row[w2];
            rank += (v2 > v || (v2 == v && w2 < w)) ? 1 : 0;
        }
        incid[e] = (rank < TOPK) ? expf(v - rmx[k * VT + u]) : 0.f;
    }
    __syncthreads();

    // phase 5: softmax row sums
    if (tid < Kk * VT) {
        int k = tid / VT, u = tid - (tid / VT) * VT;
        const float* row = incid + k * 900 + u * VT;
        float s = 0.f;
#pragma unroll 6
        for (int w = 0; w < VT; w++) s += row[w];
        rsum[tid] = 1.f / s;
    }
    __syncthreads();
    for (int e = tid; e < Kk * VT * VT; e += 256) {
        int k = e / 900;
        int u = (e - k * 900) / VT;
        incid[e] *= rsum[k * VT + u];
    }
    __syncthreads();

    // phase 6: column sums -> dvv ; row sums of inc_w -> rss
    for (int e = tid; e < 2 * Kk * VT; e += 256) {
        if (e < Kk * VT) {
            int k = e / VT, v = e - (e / VT) * VT;
            const float* col = incid + k * 900 + v;
            float s = 0.f;
#pragma unroll 6
            for (int u = 0; u < VT; u++) s += fabsf(col[u * VT]);
            dvv[e] = wt[e] / (s + 1e-8f);
        } else {
            int e2 = e - Kk * VT;
            int k = e2 / VT, u = e2 - (e2 / VT) * VT;
            const float* row = incid + k * 900 + u * VT;
            const float* wk = wt + k * VT;
            float s = 0.f;
#pragma unroll 6
            for (int v = 0; v < VT; v++) s += fabsf(row[v] * wk[v]);
            rss[e2] = s + 1e-8f;
        }
    }
    __syncthreads();

    // phase 7: tmp = incid * wt * dvv (A, stride 30)
    for (int e = tid; e < Kk * VT * VT; e += 256) {
        int k = e / 900;
        int v = (e - k * 900) % VT;
        A[e] = incid[e] * wt[k * VT + v] * dvv[k * VT + v];
    }
    __syncthreads();

    // phase 8: adj_full
    float ra = fmaxf(alpha[0], 0.f);
    for (int e = tid; e < Kk * VT * VT; e += 256) {
        int k = e / 900;
        int r = e - k * 900;
        int u = r / VT, w = r - u * VT;
        const float* ru = A + k * 900 + u * VT;
        const float* rw = incid + k * 900 + w * VT;
        float ha = 0.f;
#pragma unroll 6
        for (int v = 0; v < VT; v++) ha += ru[v] * rw[v];
        ha /= rss[k * VT + u];
        g_adj[n * (Kk * VT * VT) + e] = g_adjn[e] + ra * ha;
    }
}

// ---------------- kernel 3: MMA conv + aggregate (R12 exact) ----------------
__global__ __launch_bounds__(256, 4) void k_main(
    const float* __restrict__ x, const float* __restrict__ hj,
    const float* __restrict__ cdw, const float* __restrict__ cdb,
    const float* __restrict__ gam, const float* __restrict__ bet,
    float* __restrict__ out) {
    extern __shared__ char sm[];
    __nv_bfloat16* B2 = (__nv_bfloat16*)(sm + SM_B2);
    __nv_bfloat16* At = (__nv_bfloat16*)(sm + SM_AT);
    __nv_bfloat16* Wt = (__nv_bfloat16*)(sm + SM_WT);
    float* rowsA = (float*)(sm + SM_MISC);
    float* cdbs = rowsA + 28;
    float* scb = cdbs + 32;
    float* bbs = scb + 32;
    __nv_bfloat16* Xs = (__nv_bfloat16*)(sm + SM_XS);

    int bid = blockIdx.x;
    int tb = bid & 7;
    int kg = (bid >> 3) & 7;
    int n = bid >> 6;
    int tid = threadIdx.x;
    int lane = tid & 31;
    int w = tid >> 5;

    const float* gA = g_adj + (n * Kk + kg) * (VT * VT);
    for (int e = tid; e < 32 * 32; e += 256) {
        int v = e >> 5, u = e & 31;
        float val = (v < VT && u < Vv) ? gA[u * VT + v] : 0.f;
        At[v * XSTR + u] = __float2bfloat16(val);
    }
    for (int e = tid; e < 32 * 32; e += 256) {
        int o = e >> 5, c = e & 31;
        Wt[o * XSTR + c] = __float2bfloat16(cdw[(kg * OG + o) * CG + c]);
    }
    if (tid < 28) {
        float s = 0.f;
        if (tid < Vv) {
#pragma unroll
            for (int v = 0; v < VT; v++) s += gA[tid * VT + v];
        }
        rowsA[tid] = s;
    } else if (tid >= 32 && tid < 64) {
        int o = tid - 32;
        int oo = kg * OG + o;
        cdbs[o] = cdb[oo];
        scb[o] = gam[oo] * rsqrtf(1.f + 1e-5f);
        bbs[o] = bet[oo];
    }
    {
        const float4* gx4 = (const float4*)(x + ((size_t)(n * Cc + kg * CG) * Tt + tb * TBm) * Vv);
        for (int e = tid; e < 32 * 50; e += 256) {
            int c = e / 50, r4 = e - c * 50;
            float4 xv = gx4[c * 400 + r4];
            int z = r4 * 4;
            int tt = z / 25;
            int u = z - tt * 25;
            int addr = (c * 8 + tt) * XSTR + u;
#pragma unroll
            for (int i = 0; i < 4; i++) {
                Xs[addr] = __float2bfloat16((&xv.x)[i]);
                bool wrap = (u == 24);
                u = wrap ? 0 : u + 1;
                addr += wrap ? 16 : 1;
            }
        }
        {
            int c = tid >> 3;
            __nv_bfloat16* row = Xs + tid * XSTR;
#pragma unroll
            for (int j = 0; j < VNh; j++)
                row[Vv + j] = __float2bfloat16(hj[j * Cc + kg * CG + c]);
            *(unsigned*)(row + 30) = 0u;
        }
    }
    __syncthreads();

    int g = lane >> 2, t4 = lane & 3;
    int r16 = lane & 15, ch = lane >> 4;

    {
        unsigned bAt[2][2][4];
#pragma unroll
        for (int ks = 0; ks < 2; ks++)
#pragma unroll
            for (int np = 0; np < 2; np++)
                ldsm4t(bAt[ks][np], smaddr(At + (ks * 16 + r16) * XSTR + np * 16 + ch * 8));
#pragma unroll
        for (int m2 = 0; m2 < 2; m2++) {
            int mi = w * 2 + m2;
            unsigned afr[2][4];
#pragma unroll
            for (int ks = 0; ks < 2; ks++)
                ldsm4(afr[ks], smaddr(Xs + (mi * 16 + r16) * XSTR + ks * 16 + ch * 8));
            float D[4][4];
#pragma unroll
            for (int ni = 0; ni < 4; ni++)
#pragma unroll
                for (int i = 0; i < 4; i++) D[ni][i] = 0.f;
#pragma unroll
            for (int ks = 0; ks < 2; ks++)
#pragma unroll
                for (int ni = 0; ni < 4; ni++)
                    mma16816(D[ni], afr[ks], &bAt[ks][ni >> 1][(ni & 1) * 2]);
            int c0 = mi * 2;
#pragma unroll
            for (int ni = 0; ni < 4; ni++) {
                int u0 = ni * 8 + 2 * t4;
                int b0 = c0 * B2STR + g * Vv + u0;
                if (u0 < Vv) {
                    B2[b0] = __float2bfloat16(D[ni][0]);
                    B2[b0 + B2STR] = __float2bfloat16(D[ni][2]);
                }
                if (u0 + 1 < Vv) {
                    B2[b0 + 1] = __float2bfloat16(D[ni][1]);
                    B2[b0 + B2STR + 1] = __float2bfloat16(D[ni][3]);
                }
            }
        }
    }
    __syncthreads();

    {
        const float* xb = x + ((size_t)(n * Cc + kg * OG) * Tt + tb * TBm) * Vv;
        float* ob = out + ((size_t)(n * Cc + kg * OG) * Tt + tb * TBm) * Vv;

        unsigned aW[2][2][4];
#pragma unroll
        for (int mi2 = 0; mi2 < 2; mi2++)
#pragma unroll
            for (int ks = 0; ks < 2; ks++)
                ldsm4(aW[mi2][ks], smaddr(Wt + (mi2 * 16 + r16) * XSTR + ks * 16 + ch * 8));
        for (int j = w; j < 25; j += 8) {
            float E[2][4];
#pragma unroll
            for (int mi2 = 0; mi2 < 2; mi2++)
#pragma unroll
                for (int i = 0; i < 4; i++) E[mi2][i] = 0.f;
#pragma unroll
            for (int ks = 0; ks < 2; ks++) {
                unsigned bB[2];
                ldsm2t(bB, smaddr(B2 + (ks * 16 + r16) * B2STR + j * 8));
#pragma unroll
                for (int mi2 = 0; mi2 < 2; mi2++) mma16816(E[mi2], aW[mi2][ks], bB);
            }
            int tu = j * 8 + 2 * t4;
            int u = tu % 25;
            int u1 = (u == 24) ? 0 : u + 1;
            float ra0 = rowsA[u], ra1 = rowsA[u1];
#pragma unroll
            for (int mi2 = 0; mi2 < 2; mi2++) {
#pragma unroll
                for (int half = 0; half < 2; half++) {
                    int o = mi2 * 16 + g + 8 * half;
                    float cb = cdbs[o], sc = scb[o], bb = bbs[o];
                    float2 xv = *(const float2*)(xb + o * (Tt * Vv) + tu);
                    float y0 = E[mi2][2 * half] + cb * ra0;
                    float y1 = E[mi2][2 * half + 1] + cb * ra1;
                    float2 ov;
                    ov.x = fmaxf(y0 * sc + bb + xv.x, 0.f);
                    ov.y = fmaxf(y1 * sc + bb + xv.y, 0.f);
                    *(float2*)(ob + o * (Tt * Vv) + tu) = ov;
                }
            }
        }
    }
}

// ---------------- launch ----------------
extern "C" void kernel_launch(void* const* d_in, const int* in_sizes, int n_in,
                              void* d_out, int out_size) {
    const float* x    = (const float*)d_in[0];
    const float* adjc = (const float*)d_in[1];
    const float* ei   = (const float*)d_in[2];
    const float* hj   = (const float*)d_in[3];
    const float* alp  = (const float*)d_in[4];
    const float* tvw  = (const float*)d_in[5];
    const float* tvb  = (const float*)d_in[6];
    const float* t1w  = (const float*)d_in[7];
    const float* t1b  = (const float*)d_in[8];
    const float* t2w  = (const float*)d_in[9];
    const float* t2b  = (const float*)d_in[10];
    const float* cdw  = (const float*)d_in[11];
    const float* cdb  = (const float*)d_in[12];
    const float* gam  = (const float*)d_in[13];
    const float* bet  = (const float*)d_in[14];
    float* out = (float*)d_out;

    int tail = out_size - Nn * OO * Tt * Vv;
    k_pool<<<Nn * Cc / 2 + 1, 256>>>(x, hj, adjc, ei, out, tail);

    cudaFuncSetAttribute(k_hN, cudaFuncAttributeMaxDynamicSharedMemorySize, HN_BYTES);
    k_hN<<<Nn, 256, HN_BYTES>>>(tvw, tvb, t1w, t1b, t2w, t2b, alp);

    cudaFuncSetAttribute(k_main, cudaFuncAttributeMaxDynamicSharedMemorySize, SM_BYTES);
    k_main<<<Nn * Kk * (Tt / TBm), 256, SM_BYTES>>>(x, hj, cdw, cdb, gam, bet, out);
}

// round 16
// speedup vs baseline: 1.2583x; 1.2583x over previous
#include <cuda_runtime.h>
#include <cuda_bf16.h>
#include <math.h>

#define Nn 64
#define Cc 256
#define Tt 64
#define Vv 25
#define Kk 8
#define VNh 5
#define VT 30
#define CG 32
#define HH 8
#define OO 256
#define OG 32
#define TOPK 9

// ---- k_main (MMA) constants (R12 layout) ----
#define TBm 8
#define XSTR 40
#define B2STR 200
#define SM_B2 0
#define SM_AT 12800
#define SM_WT 15360
#define SM_MISC 17920
#define SM_XS 18432
#define SM_BYTES (18432 + 20480)   // 38912

// ---------------- device scratch ----------------
__device__ float g_pooled[Nn * Cc * VT];
__device__ float g_adjn[Kk * VT * VT];
__device__ float g_adj[Nn * Kk * VT * VT];
__device__ float g_vproj[Nn * Kk * VT * HH];
__device__ float g_w1[Nn * Kk * HH * VT];

// ---------------- mma helpers ----------------
__device__ __forceinline__ unsigned smaddr(const void* p) {
    return (unsigned)__cvta_generic_to_shared(p);
}
__device__ __forceinline__ void ldsm4(unsigned* r, unsigned a) {
    asm volatile("ldmatrix.sync.aligned.m8n8.x4.shared.b16 {%0,%1,%2,%3}, [%4];"
                 : "=r"(r[0]), "=r"(r[1]), "=r"(r[2]), "=r"(r[3]) : "r"(a));
}
__device__ __forceinline__ void ldsm4t(unsigned* r, unsigned a) {
    asm volatile("ldmatrix.sync.aligned.m8n8.x4.trans.shared.b16 {%0,%1,%2,%3}, [%4];"
                 : "=r"(r[0]), "=r"(r[1]), "=r"(r[2]), "=r"(r[3]) : "r"(a));
}
__device__ __forceinline__ void ldsm2t(unsigned* r, unsigned a) {
    asm volatile("ldmatrix.sync.aligned.m8n8.x2.trans.shared.b16 {%0,%1}, [%2];"
                 : "=r"(r[0]), "=r"(r[1]) : "r"(a));
}
__device__ __forceinline__ void mma16816(float* d, const unsigned* a, const unsigned* b) {
    asm volatile(
        "mma.sync.aligned.m16n8k16.row.col.f32.bf16.bf16.f32 "
        "{%0,%1,%2,%3}, {%4,%5,%6,%7}, {%8,%9}, {%0,%1,%2,%3};"
        : "+f"(d[0]), "+f"(d[1]), "+f"(d[2]), "+f"(d[3])
        : "r"(a[0]), "r"(a[1]), "r"(a[2]), "r"(a[3]), "r"(b[0]), "r"(b[1]));
}

// ---------------- kernel 1: pooled mean, float4 streaming (+ adjn/tail) ----------------
// 8 channels per block (one warp each). Lanes 0..24 own one float4 column,
// summing 16 rows of stride 100 floats; 4-phase combine via smem.
__global__ __launch_bounds__(256) void k_pool(const float* __restrict__ x,
                                              const float* __restrict__ hj,
                                              const float* __restrict__ adjc,
                                              const float* __restrict__ ei,
                                              float* __restrict__ out, int tail) {
    int tid = threadIdx.x;
    if (blockIdx.x == Nn * Cc / 8) {
        if (tid < Kk * VT) {
            int base = tid * VT;
            float row[VT];
            float s = 0.f;
#pragma unroll
            for (int w = 0; w < VT; w++) {
                float v = ei[base + w] * adjc[base + w];
                row[w] = v;
                s += fabsf(v);
            }
            float inv = 1.f / (s + 1e-8f);
#pragma unroll
            for (int w = 0; w < VT; w++) g_adjn[base + w] = row[w] * inv;
        }
        for (int i = tid; i < tail && i < VNh * Cc; i += 256)
            out[(size_t)Nn * OO * Tt * Vv + i] = hj[i];
        return;
    }
    __shared__ float sred[8][100];
    int ch = tid >> 5;
    int lane = tid & 31;
    int nc = blockIdx.x * 8 + ch;             // flat n*Cc + c
    if (lane < 25) {
        const float4* base4 = (const float4*)(x + (size_t)nc * (Tt * Vv)) + lane;
        float4 s = base4[0];
#pragma unroll
        for (int r = 1; r < 16; r++) {
            float4 v = base4[r * 25];
            s.x += v.x; s.y += v.y; s.z += v.z; s.w += v.w;
        }
        *(float4*)&sred[ch][lane * 4] = s;
    }
    __syncthreads();
    if (lane < Vv) {
        float s = (sred[ch][lane] + sred[ch][lane + 25]) +
                  (sred[ch][lane + 50] + sred[ch][lane + 75]);
        g_pooled[nc * VT + lane] = s * (1.f / (float)Tt);
    } else if (lane < VT) {
        g_pooled[nc * VT + lane] = hj[(lane - Vv) * Cc + (nc & (Cc - 1))];
    }
}

// ---------------- kernel 2a: vproj + w1 per (n,k) ----------------
__global__ __launch_bounds__(256) void k_hA(
    const float* __restrict__ tvw, const float* __restrict__ tvb,
    const float* __restrict__ t1w, const float* __restrict__ t1b) {
    __shared__ float ps[CG * VT];
    int n = blockIdx.x >> 3;
    int k = blockIdx.x & 7;
    int tid = threadIdx.x;

    for (int e = tid; e < CG * VT; e += 256)
        ps[e] = g_pooled[(n * Cc + k * CG) * VT + e];
    __syncthreads();

    for (int e = tid; e < 2 * VT * HH; e += 256) {
        if (e < VT * HH) {
            int v = e >> 3, h = e & 7;
            float acc = tvb[k * HH + h];
            const float* w = tvw + (k * HH + h) * CG;
#pragma unroll 8
            for (int c = 0; c < CG; c++) acc += ps[c * VT + v] * w[c];
            g_vproj[((n * Kk + k) * VT + v) * HH + h] = acc;
        } else {
            int e2 = e - VT * HH;
            int h = e2 / VT, v = e2 % VT;
            float acc = t1b[k * HH + h];
            const float* w = t1w + (k * HH + h) * CG;
#pragma unroll 8
            for (int c = 0; c < CG; c++) acc += ps[c * VT + v] * w[c];
            g_w1[(n * (Kk * HH) + k * HH + h) * VT + v] =
                (acc >= 0.f) ? acc : 0.01f * acc;
        }
    }
}

// ---------------- kernel 2b: rank-parallel top-k -> adj_full per (n,k) ----------------
__global__ __launch_bounds__(256) void k_hB(
    const float* __restrict__ t2w, const float* __restrict__ t2b,
    const float* __restrict__ alpha) {
    __shared__ float w1a[Kk * HH * VT];
    __shared__ float vp[VT * HH];
    __shared__ float t2[Kk * HH];
    __shared__ float nd[VT * 33];
    __shared__ float incid[VT * VT];
    __shared__ float tmp[VT * VT];
    __shared__ float wt[VT], dvv[VT], rss[VT], rmx[VT], rsum[VT];

    int n = blockIdx.x >> 3;
    int k = blockIdx.x & 7;
    int tid = threadIdx.x;

    for (int e = tid; e < Kk * HH * VT; e += 256) w1a[e] = g_w1[n * (Kk * HH * VT) + e];
    for (int e = tid; e < VT * HH; e += 256) vp[e] = g_vproj[(n * Kk + k) * (VT * HH) + e];
    if (tid >= 128 && tid < 128 + Kk * HH) t2[tid - 128] = t2w[k * (Kk * HH) + tid - 128];
    __syncthreads();

    if (tid < VT) {
        float acc = t2b[k];
#pragma unroll 8
        for (int q = 0; q < Kk * HH; q++) acc += w1a[q * VT + tid] * t2[q];
        wt[tid] = tanhf(acc);
    }
    for (int e = tid; e < VT * VT; e += 256) {
        int u = e / VT, w = e - u * VT;
        float d2 = 0.f;
#pragma unroll
        for (int h = 0; h < HH; h++) {
            float df = vp[u * HH + h] - vp[w * HH + h];
            d2 += df * df;
        }
        nd[u * 33 + w] = (d2 > 0.f) ? -sqrtf(d2) : 0.f;
    }
    __syncthreads();

    if (tid < VT) {
        float m = -INFINITY;
#pragma unroll 6
        for (int w = 0; w < VT; w++) m = fmaxf(m, nd[tid * 33 + w]);
        rmx[tid] = m;
    }
    __syncthreads();

    for (int e = tid; e < VT * VT; e += 256) {
        int u = e / VT, w = e - u * VT;
        float v = nd[u * 33 + w];
        int rank = 0;
#pragma unroll 6
        for (int w2 = 0; w2 < VT; w2++) {
            float v2 = nd[u * 33 + w2];
            rank += (v2 > v || (v2 == v && w2 < w)) ? 1 : 0;
        }
        incid[e] = (rank < TOPK) ? expf(v - rmx[u]) : 0.f;
    }
    __syncthreads();

    if (tid < VT) {
        float s = 0.f;
#pragma unroll 6
        for (int w = 0; w < VT; w++) s += incid[tid * VT + w];
        rsum[tid] = 1.f / s;
    }
    __syncthreads();
    for (int e = tid; e < VT * VT; e += 256) incid[e] *= rsum[e / VT];
    __syncthreads();

    if (tid < 2 * VT) {
        if (tid < VT) {
            float s = 0.f;
#pragma unroll 6
            for (int u = 0; u < VT; u++) s += fabsf(incid[u * VT + tid]);
            dvv[tid] = wt[tid] / (s + 1e-8f);
        } else {
            int u = tid - VT;
            float s = 0.f;
#pragma unroll 6
            for (int v = 0; v < VT; v++) s += fabsf(incid[u * VT + v] * wt[v]);
            rss[u] = s + 1e-8f;
        }
    }
    __syncthreads();
    for (int e = tid; e < VT * VT; e += 256) tmp[e] = incid[e] * wt[e % VT] * dvv[e % VT];
    __syncthreads();

    float ra = fmaxf(alpha[0], 0.f);
    for (int e = tid; e < VT * VT; e += 256) {
        int u = e / VT, w = e - u * VT;
        const float* ru = tmp + u * VT;
        const float* rw = incid + w * VT;
        float ha = 0.f;
#pragma unroll 6
        for (int v = 0; v < VT; v++) ha += ru[v] * rw[v];
        ha /= rss[u];
        g_adj[(n * Kk + k) * (VT * VT) + e] = g_adjn[k * (VT * VT) + e] + ra * ha;
    }
}

// ---------------- kernel 3: MMA conv + aggregate (R12 exact) ----------------
__global__ __launch_bounds__(256, 4) void k_main(
    const float* __restrict__ x, const float* __restrict__ hj,
    const float* __restrict__ cdw, const float* __restrict__ cdb,
    const float* __restrict__ gam, const float* __restrict__ bet,
    float* __restrict__ out) {
    extern __shared__ char sm[];
    __nv_bfloat16* B2 = (__nv_bfloat16*)(sm + SM_B2);
    __nv_bfloat16* At = (__nv_bfloat16*)(sm + SM_AT);
    __nv_bfloat16* Wt = (__nv_bfloat16*)(sm + SM_WT);
    float* rowsA = (float*)(sm + SM_MISC);
    float* cdbs = rowsA + 28;
    float* scb = cdbs + 32;
    float* bbs = scb + 32;
    __nv_bfloat16* Xs = (__nv_bfloat16*)(sm + SM_XS);

    int bid = blockIdx.x;
    int tb = bid & 7;
    int kg = (bid >> 3) & 7;
    int n = bid >> 6;
    int tid = threadIdx.x;
    int lane = tid & 31;
    int w = tid >> 5;

    const float* gA = g_adj + (n * Kk + kg) * (VT * VT);
    for (int e = tid; e < 32 * 32; e += 256) {
        int v = e >> 5, u = e & 31;
        float val = (v < VT && u < Vv) ? gA[u * VT + v] : 0.f;
        At[v * XSTR + u] = __float2bfloat16(val);
    }
    for (int e = tid; e < 32 * 32; e += 256) {
        int o = e >> 5, c = e & 31;
        Wt[o * XSTR + c] = __float2bfloat16(cdw[(kg * OG + o) * CG + c]);
    }
    if (tid < 28) {
        float s = 0.f;
        if (tid < Vv) {
#pragma unroll
            for (int v = 0; v < VT; v++) s += gA[tid * VT + v];
        }
        rowsA[tid] = s;
    } else if (tid >= 32 && tid < 64) {
        int o = tid - 32;
        int oo = kg * OG + o;
        cdbs[o] = cdb[oo];
        scb[o] = gam[oo] * rsqrtf(1.f + 1e-5f);
        bbs[o] = bet[oo];
    }
    {
        const float4* gx4 = (const float4*)(x + ((size_t)(n * Cc + kg * CG) * Tt + tb * TBm) * Vv);
        for (int e = tid; e < 32 * 50; e += 256) {
            int c = e / 50, r4 = e - c * 50;
            float4 xv = gx4[c * 400 + r4];
            int z = r4 * 4;
            int tt = z / 25;
            int u = z - tt * 25;
            int addr = (c * 8 + tt) * XSTR + u;
#pragma unroll
            for (int i = 0; i < 4; i++) {
                Xs[addr] = __float2bfloat16((&xv.x)[i]);
                bool wrap = (u == 24);
                u = wrap ? 0 : u + 1;
                addr += wrap ? 16 : 1;
            }
        }
        {
            int c = tid >> 3;
            __nv_bfloat16* row = Xs + tid * XSTR;
#pragma unroll
            for (int j = 0; j < VNh; j++)
                row[Vv + j] = __float2bfloat16(hj[j * Cc + kg * CG + c]);
            *(unsigned*)(row + 30) = 0u;
        }
    }
    __syncthreads();

    int g = lane >> 2, t4 = lane & 3;
    int r16 = lane & 15, ch = lane >> 4;

    {
        unsigned bAt[2][2][4];
#pragma unroll
        for (int ks = 0; ks < 2; ks++)
#pragma unroll
            for (int np = 0; np < 2; np++)
                ldsm4t(bAt[ks][np], smaddr(At + (ks * 16 + r16) * XSTR + np * 16 + ch * 8));
#pragma unroll
        for (int m2 = 0; m2 < 2; m2++) {
            int mi = w * 2 + m2;
            unsigned afr[2][4];
#pragma unroll
            for (int ks = 0; ks < 2; ks++)
                ldsm4(afr[ks], smaddr(Xs + (mi * 16 + r16) * XSTR + ks * 16 + ch * 8));
            float D[4][4];
#pragma unroll
            for (int ni = 0; ni < 4; ni++)
#pragma unroll
                for (int i = 0; i < 4; i++) D[ni][i] = 0.f;
#pragma unroll
            for (int ks = 0; ks < 2; ks++)
#pragma unroll
                for (int ni = 0; ni < 4; ni++)
                    mma16816(D[ni], afr[ks], &bAt[ks][ni >> 1][(ni & 1) * 2]);
            int c0 = mi * 2;
#pragma unroll
            for (int ni = 0; ni < 4; ni++) {
                int u0 = ni * 8 + 2 * t4;
                int b0 = c0 * B2STR + g * Vv + u0;
                if (u0 < Vv) {
                    B2[b0] = __float2bfloat16(D[ni][0]);
                    B2[b0 + B2STR] = __float2bfloat16(D[ni][2]);
                }
                if (u0 + 1 < Vv) {
                    B2[b0 + 1] = __float2bfloat16(D[ni][1]);
                    B2[b0 + B2STR + 1] = __float2bfloat16(D[ni][3]);
                }
            }
        }
    }
    __syncthreads();

    {
        const float* xb = x + ((size_t)(n * Cc + kg * OG) * Tt + tb * TBm) * Vv;
        float* ob = out + ((size_t)(n * Cc + kg * OG) * Tt + tb * TBm) * Vv;

        unsigned aW[2][2][4];
#pragma unroll
        for (int mi2 = 0; mi2 < 2; mi2++)
#pragma unroll
            for (int ks = 0; ks < 2; ks++)
                ldsm4(aW[mi2][ks], smaddr(Wt + (mi2 * 16 + r16) * XSTR + ks * 16 + ch * 8));
        for (int j = w; j < 25; j += 8) {
            float E[2][4];
#pragma unroll
            for (int mi2 = 0; mi2 < 2; mi2++)
#pragma unroll
                for (int i = 0; i < 4; i++) E[mi2][i] = 0.f;
#pragma unroll
            for (int ks = 0; ks < 2; ks++) {
                unsigned bB[2];
                ldsm2t(bB, smaddr(B2 + (ks * 16 + r16) * B2STR + j * 8));
#pragma unroll
                for (int mi2 = 0; mi2 < 2; mi2++) mma16816(E[mi2], aW[mi2][ks], bB);
            }
            int tu = j * 8 + 2 * t4;
            int u = tu % 25;
            int u1 = (u == 24) ? 0 : u + 1;
            float ra0 = rowsA[u], ra1 = rowsA[u1];
#pragma unroll
            for (int mi2 = 0; mi2 < 2; mi2++) {
#pragma unroll
                for (int half = 0; half < 2; half++) {
                    int o = mi2 * 16 + g + 8 * half;
                    float cb = cdbs[o], sc = scb[o], bb = bbs[o];
                    float2 xv = *(const float2*)(xb + o * (Tt * Vv) + tu);
                    float y0 = E[mi2][2 * half] + cb * ra0;
                    float y1 = E[mi2][2 * half + 1] + cb * ra1;
                    float2 ov;
                    ov.x = fmaxf(y0 * sc + bb + xv.x, 0.f);
                    ov.y = fmaxf(y1 * sc + bb + xv.y, 0.f);
                    *(float2*)(ob + o * (Tt * Vv) + tu) = ov;
                }
            }
        }
    }
}

// ---------------- launch ----------------
extern "C" void kernel_launch(void* const* d_in, const int* in_sizes, int n_in,
                              void* d_out, int out_size) {
    const float* x    = (const float*)d_in[0];
    const float* adjc = (const float*)d_in[1];
    const float* ei   = (const float*)d_in[2];
    const float* hj   = (const float*)d_in[3];
    const float* alp  = (const float*)d_in[4];
    const float* tvw  = (const float*)d_in[5];
    const float* tvb  = (const float*)d_in[6];
    const float* t1w  = (const float*)d_in[7];
    const float* t1b  = (const float*)d_in[8];
    const float* t2w  = (const float*)d_in[9];
    const float* t2b  = (const float*)d_in[10];
    const float* cdw  = (const float*)d_in[11];
    const float* cdb  = (const float*)d_in[12];
    const float* gam  = (const float*)d_in[13];
    const float* bet  = (const float*)d_in[14];
    float* out = (float*)d_out;

    int tail = out_size - Nn * OO * Tt * Vv;
    k_pool<<<Nn * Cc / 8 + 1, 256>>>(x, hj, adjc, ei, out, tail);
    k_hA<<<Nn * Kk, 256>>>(tvw, tvb, t1w, t1b);
    k_hB<<<Nn * Kk, 256>>>(t2w, t2b, alp);

    cudaFuncSetAttribute(k_main, cudaFuncAttributeMaxDynamicSharedMemorySize, SM_BYTES);
    k_main<<<Nn * Kk * (Tt / TBm), 256, SM_BYTES>>>(x, hj, cdw, cdb, gam, bet, out);
}

// round 17
// speedup vs baseline: 1.3862x; 1.1016x over previous
#include <cuda_runtime.h>
#include <cuda_bf16.h>
#include <math.h>

#define Nn 64
#define Cc 256
#define Tt 64
#define Vv 25
#define Kk 8
#define VNh 5
#define VT 30
#define CG 32
#define HH 8
#define OO 256
#define OG 32
#define TOPK 9

// ---- k_main (MMA) constants (R12/R16 layout) ----
#define TBm 8
#define XSTR 40
#define B2STR 200
#define SM_B2 0
#define SM_AT 12800
#define SM_WT 15360
#define SM_MISC 17920
#define SM_XS 18432
#define SM_BYTES (18432 + 20480)   // 38912

// ---------------- device scratch ----------------
__device__ float g_adjn[Kk * VT * VT];
__device__ float g_adj[Nn * Kk * VT * VT];
__device__ float g_vproj[Nn * Kk * VT * HH];
__device__ float g_w1[Nn * Kk * HH * VT];

// ---------------- mma helpers ----------------
__device__ __forceinline__ unsigned smaddr(const void* p) {
    return (unsigned)__cvta_generic_to_shared(p);
}
__device__ __forceinline__ void ldsm4(unsigned* r, unsigned a) {
    asm volatile("ldmatrix.sync.aligned.m8n8.x4.shared.b16 {%0,%1,%2,%3}, [%4];"
                 : "=r"(r[0]), "=r"(r[1]), "=r"(r[2]), "=r"(r[3]) : "r"(a));
}
__device__ __forceinline__ void ldsm4t(unsigned* r, unsigned a) {
    asm volatile("ldmatrix.sync.aligned.m8n8.x4.trans.shared.b16 {%0,%1,%2,%3}, [%4];"
                 : "=r"(r[0]), "=r"(r[1]), "=r"(r[2]), "=r"(r[3]) : "r"(a));
}
__device__ __forceinline__ void ldsm2t(unsigned* r, unsigned a) {
    asm volatile("ldmatrix.sync.aligned.m8n8.x2.trans.shared.b16 {%0,%1}, [%2];"
                 : "=r"(r[0]), "=r"(r[1]) : "r"(a));
}
__device__ __forceinline__ void mma16816(float* d, const unsigned* a, const unsigned* b) {
    asm volatile(
        "mma.sync.aligned.m16n8k16.row.col.f32.bf16.bf16.f32 "
        "{%0,%1,%2,%3}, {%4,%5,%6,%7}, {%8,%9}, {%0,%1,%2,%3};"
        : "+f"(d[0]), "+f"(d[1]), "+f"(d[2]), "+f"(d[3])
        : "r"(a[0]), "r"(a[1]), "r"(a[2]), "r"(a[3]), "r"(b[0]), "r"(b[1]));
}

// ---------------- kernel 1: fused pooling + vproj + w1 per (n,k) (+ adjn/tail) ----------------
__global__ __launch_bounds__(256) void k_poolA(
    const float* __restrict__ x, const float* __restrict__ hj,
    const float* __restrict__ adjc, const float* __restrict__ ei,
    const float* __restrict__ tvw, const float* __restrict__ tvb,
    const float* __restrict__ t1w, const float* __restrict__ t1b,
    float* __restrict__ out, int tail) {
    int tid = threadIdx.x;
    if (blockIdx.x == Nn * Kk) {
        if (tid < Kk * VT) {
            int base = tid * VT;
            float row[VT];
            float s = 0.f;
#pragma unroll
            for (int w = 0; w < VT; w++) {
                float v = ei[base + w] * adjc[base + w];
                row[w] = v;
                s += fabsf(v);
            }
            float inv = 1.f / (s + 1e-8f);
#pragma unroll
            for (int w = 0; w < VT; w++) g_adjn[base + w] = row[w] * inv;
        }
        for (int i = tid; i < tail && i < VNh * Cc; i += 256)
            out[(size_t)Nn * OO * Tt * Vv + i] = hj[i];
        return;
    }
    __shared__ float sred[8][100];
    __shared__ float ps[CG * VT];   // pooled slice for this (n,k)
    int n = blockIdx.x >> 3;
    int k = blockIdx.x & 7;
    int ch = tid >> 5;
    int lane = tid & 31;

    // 4 passes of 8 channels: float4 strided pooling -> ps
#pragma unroll
    for (int p = 0; p < 4; p++) {
        int nc = n * Cc + k * CG + p * 8 + ch;
        if (lane < 25) {
            const float4* b4 = (const float4*)(x + (size_t)nc * (Tt * Vv)) + lane;
            float4 s = b4[0];
#pragma unroll
            for (int r = 1; r < 16; r++) {
                float4 v = b4[r * 25];
                s.x += v.x; s.y += v.y; s.z += v.z; s.w += v.w;
            }
            *(float4*)&sred[ch][lane * 4] = s;
        }
        __syncthreads();
        if (tid < 200) {
            int c2 = tid / 25, v = tid - (tid / 25) * 25;
            float s = (sred[c2][v] + sred[c2][v + 25]) +
                      (sred[c2][v + 50] + sred[c2][v + 75]);
            ps[(p * 8 + c2) * VT + v] = s * (1.f / (float)Tt);
        } else if (tid < 240) {
            int e = tid - 200;
            int c2 = e / VNh, j = e - (e / VNh) * VNh;
            ps[(p * 8 + c2) * VT + Vv + j] = hj[j * Cc + k * CG + p * 8 + c2];
        }
        __syncthreads();
    }

    // vproj + w1 (exact k_hA arithmetic, reading ps)
    for (int e = tid; e < 2 * VT * HH; e += 256) {
        if (e < VT * HH) {
            int v = e >> 3, h = e & 7;
            float acc = tvb[k * HH + h];
            const float* w = tvw + (k * HH + h) * CG;
#pragma unroll 8
            for (int c = 0; c < CG; c++) acc += ps[c * VT + v] * w[c];
            g_vproj[((n * Kk + k) * VT + v) * HH + h] = acc;
        } else {
            int e2 = e - VT * HH;
            int h = e2 / VT, v = e2 % VT;
            float acc = t1b[k * HH + h];
            const float* w = t1w + (k * HH + h) * CG;
#pragma unroll 8
            for (int c = 0; c < CG; c++) acc += ps[c * VT + v] * w[c];
            g_w1[(n * (Kk * HH) + k * HH + h) * VT + v] =
                (acc >= 0.f) ? acc : 0.01f * acc;
        }
    }
}

// ---------------- kernel 2: rank-parallel top-k -> adj_full per (n,k) ----------------
__global__ __launch_bounds__(256) void k_hB(
    const float* __restrict__ t2w, const float* __restrict__ t2b,
    const float* __restrict__ alpha) {
    __shared__ float w1a[Kk * HH * VT];
    __shared__ float vp[VT * HH];
    __shared__ float t2[Kk * HH];
    __shared__ float nd[VT * 33];
    __shared__ float incid[VT * VT];
    __shared__ float tmp[VT * VT];
    __shared__ float wt[VT], dvv[VT], rss[VT], rmx[VT], rsum[VT];

    int n = blockIdx.x >> 3;
    int k = blockIdx.x & 7;
    int tid = threadIdx.x;

    for (int e = tid; e < Kk * HH * VT; e += 256) w1a[e] = g_w1[n * (Kk * HH * VT) + e];
    for (int e = tid; e < VT * HH; e += 256) vp[e] = g_vproj[(n * Kk + k) * (VT * HH) + e];
    if (tid >= 128 && tid < 128 + Kk * HH) t2[tid - 128] = t2w[k * (Kk * HH) + tid - 128];
    __syncthreads();

    if (tid < VT) {
        float acc = t2b[k];
#pragma unroll 8
        for (int q = 0; q < Kk * HH; q++) acc += w1a[q * VT + tid] * t2[q];
        wt[tid] = tanhf(acc);
    }
    for (int e = tid; e < VT * VT; e += 256) {
        int u = e / VT, w = e - u * VT;
        float d2 = 0.f;
#pragma unroll
        for (int h = 0; h < HH; h++) {
            float df = vp[u * HH + h] - vp[w * HH + h];
            d2 += df * df;
        }
        nd[u * 33 + w] = (d2 > 0.f) ? -sqrtf(d2) : 0.f;
    }
    __syncthreads();

    if (tid < VT) {
        float m = -INFINITY;
#pragma unroll 6
        for (int w = 0; w < VT; w++) m = fmaxf(m, nd[tid * 33 + w]);
        rmx[tid] = m;
    }
    __syncthreads();

    for (int e = tid; e < VT * VT; e += 256) {
        int u = e / VT, w = e - u * VT;
        float v = nd[u * 33 + w];
        int rank = 0;
#pragma unroll 6
        for (int w2 = 0; w2 < VT; w2++) {
            float v2 = nd[u * 33 + w2];
            rank += (v2 > v || (v2 == v && w2 < w)) ? 1 : 0;
        }
        incid[e] = (rank < TOPK) ? expf(v - rmx[u]) : 0.f;
    }
    __syncthreads();

    if (tid < VT) {
        float s = 0.f;
#pragma unroll 6
        for (int w = 0; w < VT; w++) s += incid[tid * VT + w];
        rsum[tid] = 1.f / s;
    }
    __syncthreads();
    for (int e = tid; e < VT * VT; e += 256) incid[e] *= rsum[e / VT];
    __syncthreads();

    if (tid < 2 * VT) {
        if (tid < VT) {
            float s = 0.f;
#pragma unroll 6
            for (int u = 0; u < VT; u++) s += fabsf(incid[u * VT + tid]);
            dvv[tid] = wt[tid] / (s + 1e-8f);
        } else {
            int u = tid - VT;
            float s = 0.f;
#pragma unroll 6
            for (int v = 0; v < VT; v++) s += fabsf(incid[u * VT + v] * wt[v]);
            rss[u] = s + 1e-8f;
        }
    }
    __syncthreads();
    for (int e = tid; e < VT * VT; e += 256) tmp[e] = incid[e] * wt[e % VT] * dvv[e % VT];
    __syncthreads();

    float ra = fmaxf(alpha[0], 0.f);
    for (int e = tid; e < VT * VT; e += 256) {
        int u = e / VT, w = e - u * VT;
        const float* ru = tmp + u * VT;
        const float* rw = incid + w * VT;
        float ha = 0.f;
#pragma unroll 6
        for (int v = 0; v < VT; v++) ha += ru[v] * rw[v];
        ha /= rss[u];
        g_adj[(n * Kk + k) * (VT * VT) + e] = g_adjn[k * (VT * VT) + e] + ra * ha;
    }
}

// ---------------- kernel 3: MMA conv + aggregate (R12/R16 exact) ----------------
__global__ __launch_bounds__(256, 4) void k_main(
    const float* __restrict__ x, const float* __restrict__ hj,
    const float* __restrict__ cdw, const float* __restrict__ cdb,
    const float* __restrict__ gam, const float* __restrict__ bet,
    float* __restrict__ out) {
    extern __shared__ char sm[];
    __nv_bfloat16* B2 = (__nv_bfloat16*)(sm + SM_B2);
    __nv_bfloat16* At = (__nv_bfloat16*)(sm + SM_AT);
    __nv_bfloat16* Wt = (__nv_bfloat16*)(sm + SM_WT);
    float* rowsA = (float*)(sm + SM_MISC);
    float* cdbs = rowsA + 28;
    float* scb = cdbs + 32;
    float* bbs = scb + 32;
    __nv_bfloat16* Xs = (__nv_bfloat16*)(sm + SM_XS);

    int bid = blockIdx.x;
    int tb = bid & 7;
    int kg = (bid >> 3) & 7;
    int n = bid >> 6;
    int tid = threadIdx.x;
    int lane = tid & 31;
    int w = tid >> 5;

    const float* gA = g_adj + (n * Kk + kg) * (VT * VT);
    for (int e = tid; e < 32 * 32; e += 256) {
        int v = e >> 5, u = e & 31;
        float val = (v < VT && u < Vv) ? gA[u * VT + v] : 0.f;
        At[v * XSTR + u] = __float2bfloat16(val);
    }
    for (int e = tid; e < 32 * 32; e += 256) {
        int o = e >> 5, c = e & 31;
        Wt[o * XSTR + c] = __float2bfloat16(cdw[(kg * OG + o) * CG + c]);
    }
    if (tid < 28) {
        float s = 0.f;
        if (tid < Vv) {
#pragma unroll
            for (int v = 0; v < VT; v++) s += gA[tid * VT + v];
        }
        rowsA[tid] = s;
    } else if (tid >= 32 && tid < 64) {
        int o = tid - 32;
        int oo = kg * OG + o;
        cdbs[o] = cdb[oo];
        scb[o] = gam[oo] * rsqrtf(1.f + 1e-5f);
        bbs[o] = bet[oo];
    }
    {
        const float4* gx4 = (const float4*)(x + ((size_t)(n * Cc + kg * CG) * Tt + tb * TBm) * Vv);
        for (int e = tid; e < 32 * 50; e += 256) {
            int c = e / 50, r4 = e - c * 50;
            float4 xv = gx4[c * 400 + r4];
            int z = r4 * 4;
            int tt = z / 25;
            int u = z - tt * 25;
            int addr = (c * 8 + tt) * XSTR + u;
#pragma unroll
            for (int i = 0; i < 4; i++) {
                Xs[addr] = __float2bfloat16((&xv.x)[i]);
                bool wrap = (u == 24);
                u = wrap ? 0 : u + 1;
                addr += wrap ? 16 : 1;
            }
        }
        {
            int c = tid >> 3;
            __nv_bfloat16* row = Xs + tid * XSTR;
#pragma unroll
            for (int j = 0; j < VNh; j++)
                row[Vv + j] = __float2bfloat16(hj[j * Cc + kg * CG + c]);
            *(unsigned*)(row + 30) = 0u;
        }
    }
    __syncthreads();

    int g = lane >> 2, t4 = lane & 3;
    int r16 = lane & 15, ch = lane >> 4;

    {
        unsigned bAt[2][2][4];
#pragma unroll
        for (int ks = 0; ks < 2; ks++)
#pragma unroll
            for (int np = 0; np < 2; np++)
                ldsm4t(bAt[ks][np], smaddr(At + (ks * 16 + r16) * XSTR + np * 16 + ch * 8));
#pragma unroll
        for (int m2 = 0; m2 < 2; m2++) {
            int mi = w * 2 + m2;
            unsigned afr[2][4];
#pragma unroll
            for (int ks = 0; ks < 2; ks++)
                ldsm4(afr[ks], smaddr(Xs + (mi * 16 + r16) * XSTR + ks * 16 + ch * 8));
            float D[4][4];
#pragma unroll
            for (int ni = 0; ni < 4; ni++)
#pragma unroll
                for (int i = 0; i < 4; i++) D[ni][i] = 0.f;
#pragma unroll
            for (int ks = 0; ks < 2; ks++)
#pragma unroll
                for (int ni = 0; ni < 4; ni++)
                    mma16816(D[ni], afr[ks], &bAt[ks][ni >> 1][(ni & 1) * 2]);
            int c0 = mi * 2;
#pragma unroll
            for (int ni = 0; ni < 4; ni++) {
                int u0 = ni * 8 + 2 * t4;
                int b0 = c0 * B2STR + g * Vv + u0;
                if (u0 < Vv) {
                    B2[b0] = __float2bfloat16(D[ni][0]);
                    B2[b0 + B2STR] = __float2bfloat16(D[ni][2]);
                }
                if (u0 + 1 < Vv) {
                    B2[b0 + 1] = __float2bfloat16(D[ni][1]);
                    B2[b0 + B2STR + 1] = __float2bfloat16(D[ni][3]);
                }
            }
        }
    }
    __syncthreads();

    {
        const float* xb = x + ((size_t)(n * Cc + kg * OG) * Tt + tb * TBm) * Vv;
        float* ob = out + ((size_t)(n * Cc + kg * OG) * Tt + tb * TBm) * Vv;

        unsigned aW[2][2][4];
#pragma unroll
        for (int mi2 = 0; mi2 < 2; mi2++)
#pragma unroll
            for (int ks = 0; ks < 2; ks++)
                ldsm4(aW[mi2][ks], smaddr(Wt + (mi2 * 16 + r16) * XSTR + ks * 16 + ch * 8));
        for (int j = w; j < 25; j += 8) {
            float E[2][4];
#pragma unroll
            for (int mi2 = 0; mi2 < 2; mi2++)
#pragma unroll
                for (int i = 0; i < 4; i++) E[mi2][i] = 0.f;
#pragma unroll
            for (int ks = 0; ks < 2; ks++) {
                unsigned bB[2];
                ldsm2t(bB, smaddr(B2 + (ks * 16 + r16) * B2STR + j * 8));
#pragma unroll
                for (int mi2 = 0; mi2 < 2; mi2++) mma16816(E[mi2], aW[mi2][ks], bB);
            }
            int tu = j * 8 + 2 * t4;
            int u = tu % 25;
            int u1 = (u == 24) ? 0 : u + 1;
            float ra0 = rowsA[u], ra1 = rowsA[u1];
#pragma unroll
            for (int mi2 = 0; mi2 < 2; mi2++) {
#pragma unroll
                for (int half = 0; half < 2; half++) {
                    int o = mi2 * 16 + g + 8 * half;
                    float cb = cdbs[o], sc = scb[o], bb = bbs[o];
                    float2 xv = *(const float2*)(xb + o * (Tt * Vv) + tu);
                    float y0 = E[mi2][2 * half] + cb * ra0;
                    float y1 = E[mi2][2 * half + 1] + cb * ra1;
                    float2 ov;
                    ov.x = fmaxf(y0 * sc + bb + xv.x, 0.f);
                    ov.y = fmaxf(y1 * sc + bb + xv.y, 0.f);
                    *(float2*)(ob + o * (Tt * Vv) + tu) = ov;
                }
            }
        }
    }
}

// ---------------- launch ----------------
extern "C" void kernel_launch(void* const* d_in, const int* in_sizes, int n_in,
                              void* d_out, int out_size) {
    const float* x    = (const float*)d_in[0];
    const float* adjc = (const float*)d_in[1];
    const float* ei   = (const float*)d_in[2];
    const float* hj   = (const float*)d_in[3];
    const float* alp  = (const float*)d_in[4];
    const float* tvw  = (const float*)d_in[5];
    const float* tvb  = (const float*)d_in[6];
    const float* t1w  = (const float*)d_in[7];
    const float* t1b  = (const float*)d_in[8];
    const float* t2w  = (const float*)d_in[9];
    const float* t2b  = (const float*)d_in[10];
    const float* cdw  = (const float*)d_in[11];
    const float* cdb  = (const float*)d_in[12];
    const float* gam  = (const float*)d_in[13];
    const float* bet  = (const float*)d_in[14];
    float* out = (float*)d_out;

    int tail = out_size - Nn * OO * Tt * Vv;
    k_poolA<<<Nn * Kk + 1, 256>>>(x, hj, adjc, ei, tvw, tvb, t1w, t1b, out, tail);
    k_hB<<<Nn * Kk, 256>>>(t2w, t2b, alp);

    cudaFuncSetAttribute(k_main, cudaFuncAttributeMaxDynamicSharedMemorySize, SM_BYTES);
    k_main<<<Nn * Kk * (Tt / TBm), 256, SM_BYTES>>>(x, hj, cdw, cdb, gam, bet, out);
}